// round 1
// baseline (speedup 1.0000x reference)
#include <cuda_runtime.h>
#include <math.h>

#define Bq 2
#define Lq 2048
#define Dm 2048
#define NH 16
#define HDv 128
#define KVHv 4
#define NREPv 4
#define NE 8
#define NI 1024
#define Ttok (Bq*Lq)          /* 4096 */
#define KVD (KVHv*HDv)        /* 512  */
#define SLOTS (Ttok*2)        /* 8192 */

// ---------------- scratch (static device allocations are allowed) ----------
__device__ float g_h[Ttok*Dm];        // rmsnorm output (attn), reused for moe norm
__device__ float g_q[Ttok*Dm];
__device__ float g_k[Ttok*KVD];
__device__ float g_v[Ttok*KVD];
__device__ float g_ao[Ttok*Dm];
__device__ float g_act[SLOTS*NI];     // silu(x@w1)*(x@w3), grouped by expert
__device__ float g_y[SLOTS*Dm];       // per-slot expert output
__device__ float g_scores[Ttok*NE];
__device__ int   g_counts[NE];
__device__ int   g_offsets[NE+1];
__device__ int   g_cursor[NE];
__device__ int   g_top_idx[Ttok*2];
__device__ float g_top_w[Ttok*2];
__device__ int   g_slot_token[SLOTS];
__device__ float g_slot_w[SLOTS];
__device__ int   g_slot_of[Ttok*2];

// ---------------- utility kernels ------------------------------------------
__global__ void zero_kernel() {
    int i = threadIdx.x;
    if (i < NE) { g_counts[i] = 0; g_cursor[i] = 0; }
}

__global__ void rmsnorm_kernel(const float* __restrict__ in,
                               const float* __restrict__ w,
                               float* __restrict__ out) {
    int t = blockIdx.x;
    const float* row = in + (size_t)t*Dm;
    float ss = 0.f;
    for (int i = threadIdx.x; i < Dm; i += 256) { float v = row[i]; ss += v*v; }
    __shared__ float red[8];
    for (int o = 16; o; o >>= 1) ss += __shfl_xor_sync(0xffffffffu, ss, o);
    if ((threadIdx.x & 31) == 0) red[threadIdx.x >> 5] = ss;
    __syncthreads();
    float tot = 0.f;
    #pragma unroll
    for (int i = 0; i < 8; i++) tot += red[i];
    float inv = rsqrtf(tot * (1.f/(float)Dm) + 1e-5f);
    for (int i = threadIdx.x; i < Dm; i += 256)
        out[(size_t)t*Dm + i] = row[i] * inv * w[i];
}

// ---------------- generic SGEMM: C[M,N] = A[M,K] @ B[K,N] (+ addsrc) -------
// 128x128 tile, TK=8, 256 threads, 8x8 per thread. N%128==0, K%8==0 required.
__global__ void sgemm_kernel(const float* __restrict__ A,
                             const float* __restrict__ B,
                             float* __restrict__ C,
                             int M, int N, int K,
                             const float* __restrict__ addsrc) {
    __shared__ float As[8][128];
    __shared__ float Bs[8][128];
    int bm = blockIdx.y * 128;
    int bn = blockIdx.x * 128;
    int tid = threadIdx.x;
    int tx = tid & 15, ty = tid >> 4;
    float acc[8][8] = {};
    int a_row = tid >> 1;
    int a_col = (tid & 1) * 4;
    int b_row = tid >> 5;
    int b_col = (tid & 31) * 4;
    for (int k0 = 0; k0 < K; k0 += 8) {
        float4 av = make_float4(0.f,0.f,0.f,0.f);
        int gr = bm + a_row;
        if (gr < M) av = *(const float4*)(A + (size_t)gr*K + k0 + a_col);
        As[a_col+0][a_row] = av.x;
        As[a_col+1][a_row] = av.y;
        As[a_col+2][a_row] = av.z;
        As[a_col+3][a_row] = av.w;
        *(float4*)&Bs[b_row][b_col] = *(const float4*)(B + (size_t)(k0+b_row)*N + bn + b_col);
        __syncthreads();
        #pragma unroll
        for (int kk = 0; kk < 8; kk++) {
            float ra[8], rb[8];
            #pragma unroll
            for (int i = 0; i < 8; i++) ra[i] = As[kk][ty*8+i];
            #pragma unroll
            for (int j = 0; j < 8; j++) rb[j] = Bs[kk][tx*8+j];
            #pragma unroll
            for (int i = 0; i < 8; i++)
                #pragma unroll
                for (int j = 0; j < 8; j++)
                    acc[i][j] += ra[i]*rb[j];
        }
        __syncthreads();
    }
    for (int i = 0; i < 8; i++) {
        int r = bm + ty*8 + i;
        if (r >= M) continue;
        #pragma unroll
        for (int j = 0; j < 8; j += 4) {
            int c = bn + tx*8 + j;
            float4 o = make_float4(acc[i][j], acc[i][j+1], acc[i][j+2], acc[i][j+3]);
            if (addsrc) {
                float4 s = *(const float4*)(addsrc + (size_t)r*N + c);
                o.x += s.x; o.y += s.y; o.z += s.z; o.w += s.w;
            }
            *(float4*)(C + (size_t)r*N + c) = o;
        }
    }
}

// ---------------- RoPE (in-place on g_q and g_k) ----------------------------
__global__ void rope_kernel() {
    int idx = blockIdx.x*256 + threadIdx.x;
    const int totq = Ttok*NH*(HDv/2);
    const int tot  = totq + Ttok*KVHv*(HDv/2);
    if (idx >= tot) return;
    float* base; int t, i;
    if (idx < totq) {
        i = idx & 63;
        int hh = (idx >> 6) & (NH-1);
        t = idx >> 10;                       // 64*16
        base = g_q + (size_t)t*Dm + hh*HDv + 2*i;
    } else {
        int id2 = idx - totq;
        i = id2 & 63;
        int hh = (id2 >> 6) & (KVHv-1);
        t = id2 >> 8;                        // 64*4
        base = g_k + (size_t)t*KVD + hh*HDv + 2*i;
    }
    int pos = t & (Lq-1);
    // inv = 10000^{-i/64}
    float inv = exp2f(-(float)i * (13.287712379549449f/64.f));
    float ang = (float)pos * inv;
    float c = cosf(ang), s = sinf(ang);
    float xr = base[0], xi = base[1];
    base[0] = xr*c - xi*s;
    base[1] = xr*s + xi*c;
}

// ---------------- flash attention (fp32, warp per query) -------------------
#define KT 32
__global__ void attn_kernel() {
    __shared__ float Ks[KT][HDv];
    __shared__ float Vs[KT][HDv];
    int b = blockIdx.z, h = blockIdx.y;
    int warp = threadIdx.x >> 5, lane = threadIdx.x & 31;
    int l = blockIdx.x * 8 + warp;
    int t = b * Lq + l;
    int kvh = h >> 2;   // NREP=4
    const float scale = 0.08838834764831845f;  // 1/sqrt(128)
    float4 qv = *(const float4*)(g_q + (size_t)t*Dm + h*HDv + lane*4);
    qv.x *= scale; qv.y *= scale; qv.z *= scale; qv.w *= scale;
    float m = -1e30f, lsum = 0.f;
    float acc0 = 0.f, acc1 = 0.f, acc2 = 0.f, acc3 = 0.f;
    int maxl = blockIdx.x*8 + 7;
    int ntiles = maxl / KT + 1;
    for (int kt = 0; kt < ntiles; kt++) {
        int base = kt * KT;
        for (int idx = threadIdx.x; idx < KT*HDv/4; idx += 256) {
            int row = idx >> 5;
            int col = (idx & 31) * 4;
            size_t goff = (size_t)(b*Lq + base + row)*KVD + kvh*HDv + col;
            *(float4*)&Ks[row][col] = *(const float4*)(g_k + goff);
            *(float4*)&Vs[row][col] = *(const float4*)(g_v + goff);
        }
        __syncthreads();
        int jmax = min(KT, l - base + 1);
        for (int j = 0; j < jmax; j++) {
            float4 kv4 = *(const float4*)&Ks[j][lane*4];
            float s = qv.x*kv4.x + qv.y*kv4.y + qv.z*kv4.z + qv.w*kv4.w;
            s += __shfl_xor_sync(0xffffffffu, s, 16);
            s += __shfl_xor_sync(0xffffffffu, s, 8);
            s += __shfl_xor_sync(0xffffffffu, s, 4);
            s += __shfl_xor_sync(0xffffffffu, s, 2);
            s += __shfl_xor_sync(0xffffffffu, s, 1);
            float mn = fmaxf(m, s);
            float alpha = __expf(m - mn);
            float p = __expf(s - mn);
            lsum = lsum*alpha + p;
            float4 vv = *(const float4*)&Vs[j][lane*4];
            acc0 = acc0*alpha + p*vv.x;
            acc1 = acc1*alpha + p*vv.y;
            acc2 = acc2*alpha + p*vv.z;
            acc3 = acc3*alpha + p*vv.w;
            m = mn;
        }
        __syncthreads();
    }
    float inv = 1.f / lsum;
    float4 o = make_float4(acc0*inv, acc1*inv, acc2*inv, acc3*inv);
    *(float4*)(g_ao + (size_t)t*Dm + h*HDv + lane*4) = o;
}

// ---------------- gating ----------------------------------------------------
__global__ void gate_kernel(const float* __restrict__ gw) {
    int t = blockIdx.x;
    int warp = threadIdx.x >> 5, lane = threadIdx.x & 31;
    const float* row = g_h + (size_t)t*Dm;
    float s = 0.f;
    for (int i = lane; i < Dm; i += 32) s += row[i] * gw[(size_t)i*NE + warp];
    for (int o = 16; o; o >>= 1) s += __shfl_xor_sync(0xffffffffu, s, o);
    __shared__ float logits[NE];
    if (lane == 0) logits[warp] = s;
    __syncthreads();
    if (threadIdx.x == 0) {
        float mx = logits[0];
        for (int e = 1; e < NE; e++) mx = fmaxf(mx, logits[e]);
        float ex[NE]; float sum = 0.f;
        for (int e = 0; e < NE; e++) { ex[e] = expf(logits[e]-mx); sum += ex[e]; }
        float invs = 1.f/sum;
        float sc[NE];
        for (int e = 0; e < NE; e++) { sc[e] = ex[e]*invs; g_scores[t*NE+e] = sc[e]; }
        int e0 = 0; float m0 = sc[0];
        for (int e = 1; e < NE; e++) if (sc[e] > m0) { m0 = sc[e]; e0 = e; }
        int e1 = -1; float m1 = -1.f;
        for (int e = 0; e < NE; e++) if (e != e0 && sc[e] > m1) { m1 = sc[e]; e1 = e; }
        float wsum = m0 + m1;
        g_top_idx[t*2]   = e0;  g_top_idx[t*2+1] = e1;
        g_top_w[t*2]     = m0/wsum;
        g_top_w[t*2+1]   = m1/wsum;
        atomicAdd(&g_counts[e0], 1);
        atomicAdd(&g_counts[e1], 1);
    }
}

__global__ void finalize_gate_kernel(float* aux_out) {
    int warp = threadIdx.x >> 5, lane = threadIdx.x & 31;
    float s = 0.f;
    for (int t = lane; t < Ttok; t += 32) s += g_scores[t*NE + warp];
    for (int o = 16; o; o >>= 1) s += __shfl_xor_sync(0xffffffffu, s, o);
    __shared__ float ps[NE];
    if (lane == 0) ps[warp] = s;
    __syncthreads();
    if (threadIdx.x == 0) {
        int off = 0; float aux = 0.f;
        for (int e = 0; e < NE; e++) {
            g_offsets[e] = off; off += g_counts[e];
            float f = (float)g_counts[e] / (float)Ttok;
            float p = ps[e] / (float)Ttok;
            aux += f * p;
        }
        g_offsets[NE] = off;
        aux_out[0] = 0.01f * (float)NE * aux;
    }
}

__global__ void scatter_kernel() {
    int t = blockIdx.x*256 + threadIdx.x;
    if (t >= Ttok) return;
    for (int j = 0; j < 2; j++) {
        int e = g_top_idx[t*2+j];
        int pos = atomicAdd(&g_cursor[e], 1);
        int slot = g_offsets[e] + pos;
        g_slot_token[slot] = t;
        g_slot_w[slot] = g_top_w[t*2+j];
        g_slot_of[t*2+j] = slot;
    }
}

// ---------------- MoE gemm1: ACT = silu(Xg@W1) * (Xg@W3), grouped ----------
// tile 128x64, TK=8, 256 threads, 8x4 per thread, dual accumulators
__global__ void moe_gemm13_kernel(const float* __restrict__ w1,
                                  const float* __restrict__ w3) {
    int e = blockIdx.z;
    int cnt = g_counts[e];
    int bm = blockIdx.y * 128;
    if (bm >= cnt) return;
    int off = g_offsets[e];
    int bn = blockIdx.x * 64;
    __shared__ float As[8][128];
    __shared__ float B1s[8][64];
    __shared__ float B3s[8][64];
    int tid = threadIdx.x;
    int tx = tid & 15, ty = tid >> 4;
    float acc1[8][4] = {}; float acc3[8][4] = {};
    int a_row = tid >> 1;
    int a_col = (tid & 1) * 4;
    int tok = -1;
    if (bm + a_row < cnt) tok = g_slot_token[off + bm + a_row];
    const float* W1e = w1 + (size_t)e*Dm*NI;
    const float* W3e = w3 + (size_t)e*Dm*NI;
    for (int k0 = 0; k0 < Dm; k0 += 8) {
        float4 av = make_float4(0.f,0.f,0.f,0.f);
        if (tok >= 0) av = *(const float4*)(g_h + (size_t)tok*Dm + k0 + a_col);
        As[a_col+0][a_row] = av.x;
        As[a_col+1][a_row] = av.y;
        As[a_col+2][a_row] = av.z;
        As[a_col+3][a_row] = av.w;
        if (tid < 128) {
            int r = tid >> 4, c = (tid & 15)*4;
            *(float4*)&B1s[r][c] = *(const float4*)(W1e + (size_t)(k0+r)*NI + bn + c);
        } else {
            int t2 = tid - 128;
            int r = t2 >> 4, c = (t2 & 15)*4;
            *(float4*)&B3s[r][c] = *(const float4*)(W3e + (size_t)(k0+r)*NI + bn + c);
        }
        __syncthreads();
        #pragma unroll
        for (int kk = 0; kk < 8; kk++) {
            float ra[8], rb1[4], rb3[4];
            #pragma unroll
            for (int i = 0; i < 8; i++) ra[i] = As[kk][ty*8+i];
            #pragma unroll
            for (int j = 0; j < 4; j++) { rb1[j] = B1s[kk][tx*4+j]; rb3[j] = B3s[kk][tx*4+j]; }
            #pragma unroll
            for (int i = 0; i < 8; i++)
                #pragma unroll
                for (int j = 0; j < 4; j++) {
                    acc1[i][j] += ra[i]*rb1[j];
                    acc3[i][j] += ra[i]*rb3[j];
                }
        }
        __syncthreads();
    }
    for (int i = 0; i < 8; i++) {
        int r = bm + ty*8 + i;
        if (r >= cnt) continue;
        float4 o;
        float vals[4];
        #pragma unroll
        for (int j = 0; j < 4; j++) {
            float gg = acc1[i][j];
            float uu = acc3[i][j];
            float sg = 1.f/(1.f + expf(-gg));
            vals[j] = gg*sg*uu;
        }
        o.x = vals[0]; o.y = vals[1]; o.z = vals[2]; o.w = vals[3];
        *(float4*)(g_act + (size_t)(off+r)*NI + bn + tx*4) = o;
    }
}

// ---------------- MoE gemm2: Y = ACT @ W2, grouped --------------------------
__global__ void moe_gemm2_kernel(const float* __restrict__ w2) {
    int e = blockIdx.z;
    int cnt = g_counts[e];
    int bm = blockIdx.y * 128;
    if (bm >= cnt) return;
    int off = g_offsets[e];
    int bn = blockIdx.x * 128;
    const float* A = g_act + (size_t)off*NI;
    const float* Bw = w2 + (size_t)e*NI*Dm;
    float* C = g_y + (size_t)off*Dm;
    __shared__ float As[8][128];
    __shared__ float Bs[8][128];
    int tid = threadIdx.x;
    int tx = tid & 15, ty = tid >> 4;
    float acc[8][8] = {};
    int a_row = tid >> 1;
    int a_col = (tid & 1) * 4;
    int b_row = tid >> 5;
    int b_col = (tid & 31) * 4;
    for (int k0 = 0; k0 < NI; k0 += 8) {
        float4 av = make_float4(0.f,0.f,0.f,0.f);
        int gr = bm + a_row;
        if (gr < cnt) av = *(const float4*)(A + (size_t)gr*NI + k0 + a_col);
        As[a_col+0][a_row] = av.x;
        As[a_col+1][a_row] = av.y;
        As[a_col+2][a_row] = av.z;
        As[a_col+3][a_row] = av.w;
        *(float4*)&Bs[b_row][b_col] = *(const float4*)(Bw + (size_t)(k0+b_row)*Dm + bn + b_col);
        __syncthreads();
        #pragma unroll
        for (int kk = 0; kk < 8; kk++) {
            float ra[8], rb[8];
            #pragma unroll
            for (int i = 0; i < 8; i++) ra[i] = As[kk][ty*8+i];
            #pragma unroll
            for (int j = 0; j < 8; j++) rb[j] = Bs[kk][tx*8+j];
            #pragma unroll
            for (int i = 0; i < 8; i++)
                #pragma unroll
                for (int j = 0; j < 8; j++)
                    acc[i][j] += ra[i]*rb[j];
        }
        __syncthreads();
    }
    for (int i = 0; i < 8; i++) {
        int r = bm + ty*8 + i;
        if (r >= cnt) continue;
        #pragma unroll
        for (int j = 0; j < 8; j += 4) {
            int c = bn + tx*8 + j;
            float4 o = make_float4(acc[i][j], acc[i][j+1], acc[i][j+2], acc[i][j+3]);
            *(float4*)(C + (size_t)r*Dm + c) = o;
        }
    }
}

__global__ void final_add_kernel(float* __restrict__ out) {
    int t = blockIdx.x;
    int s0 = g_slot_of[t*2], s1 = g_slot_of[t*2+1];
    float w0 = g_slot_w[s0], w1 = g_slot_w[s1];
    for (int i = threadIdx.x*4; i < Dm; i += 256*4) {
        float4 a  = *(float4*)(out + (size_t)t*Dm + i);
        float4 y0 = *(const float4*)(g_y + (size_t)s0*Dm + i);
        float4 y1 = *(const float4*)(g_y + (size_t)s1*Dm + i);
        a.x += w0*y0.x + w1*y1.x;
        a.y += w0*y0.y + w1*y1.y;
        a.z += w0*y0.z + w1*y1.z;
        a.w += w0*y0.w + w1*y1.w;
        *(float4*)(out + (size_t)t*Dm + i) = a;
    }
}

// ---------------- launch -----------------------------------------------------
extern "C" void kernel_launch(void* const* d_in, const int* in_sizes, int n_in,
                              void* d_out, int out_size) {
    const float* x           = (const float*)d_in[0];
    const float* w_q         = (const float*)d_in[1];
    const float* w_k         = (const float*)d_in[2];
    const float* w_v         = (const float*)d_in[3];
    const float* w_o         = (const float*)d_in[4];
    const float* attn_norm_w = (const float*)d_in[5];
    const float* moe_norm_w  = (const float*)d_in[6];
    const float* gate_w      = (const float*)d_in[7];
    const float* w1          = (const float*)d_in[8];
    const float* w3          = (const float*)d_in[9];
    const float* w2          = (const float*)d_in[10];
    float* out = (float*)d_out;

    float *ph, *pq, *pk, *pv, *pao;
    cudaGetSymbolAddress((void**)&ph,  g_h);
    cudaGetSymbolAddress((void**)&pq,  g_q);
    cudaGetSymbolAddress((void**)&pk,  g_k);
    cudaGetSymbolAddress((void**)&pv,  g_v);
    cudaGetSymbolAddress((void**)&pao, g_ao);

    zero_kernel<<<1, 32>>>();
    rmsnorm_kernel<<<Ttok, 256>>>(x, attn_norm_w, ph);
    sgemm_kernel<<<dim3(Dm/128,  Ttok/128), 256>>>(ph, w_q, pq, Ttok, Dm,  Dm, nullptr);
    sgemm_kernel<<<dim3(KVD/128, Ttok/128), 256>>>(ph, w_k, pk, Ttok, KVD, Dm, nullptr);
    sgemm_kernel<<<dim3(KVD/128, Ttok/128), 256>>>(ph, w_v, pv, Ttok, KVD, Dm, nullptr);
    {
        int tot = Ttok*NH*(HDv/2) + Ttok*KVHv*(HDv/2);
        rope_kernel<<<(tot + 255)/256, 256>>>();
    }
    attn_kernel<<<dim3(Lq/8, NH, Bq), 256>>>();
    sgemm_kernel<<<dim3(Dm/128, Ttok/128), 256>>>(pao, w_o, out, Ttok, Dm, Dm, x);
    rmsnorm_kernel<<<Ttok, 256>>>(out, moe_norm_w, ph);
    gate_kernel<<<Ttok, 256>>>(gate_w);
    finalize_gate_kernel<<<1, 256>>>(out + (size_t)Ttok*Dm);
    scatter_kernel<<<(Ttok + 255)/256, 256>>>();
    moe_gemm13_kernel<<<dim3(NI/64,  SLOTS/128, NE), 256>>>(w1, w3);
    moe_gemm2_kernel <<<dim3(Dm/128, SLOTS/128, NE), 256>>>(w2);
    final_add_kernel<<<Ttok, 256>>>(out);
}

// round 2
// speedup vs baseline: 1.7308x; 1.7308x over previous
#include <cuda_runtime.h>
#include <math.h>

#define Bq 2
#define Lq 2048
#define Dm 2048
#define NH 16
#define HDv 128
#define KVHv 4
#define NE 8
#define NI 1024
#define Ttok (Bq*Lq)          /* 4096 */
#define KVD (KVHv*HDv)        /* 512  */
#define SLOTS (Ttok*2)        /* 8192 */

// ---------------- scratch ----------------
__device__ float g_h[Ttok*Dm];
__device__ float g_q[Ttok*Dm];
__device__ float g_k[Ttok*KVD];
__device__ float g_v[Ttok*KVD];
__device__ float g_ao[Ttok*Dm];
__device__ float g_g[SLOTS*NI];       // silu gate buf (in-place silu*u result)
__device__ float g_u[SLOTS*NI];
__device__ float g_y[SLOTS*Dm];
__device__ float g_scores[Ttok*NE];
__device__ int   g_counts[NE];
__device__ int   g_offsets[NE+1];
__device__ int   g_cursor[NE];
__device__ int   g_top_idx[Ttok*2];
__device__ float g_top_w[Ttok*2];
__device__ int   g_slot_token[SLOTS];
__device__ float g_slot_w[SLOTS];
__device__ int   g_slot_of[Ttok*2];

// ---------------- small kernels ----------------
__global__ void zero_kernel() {
    int i = threadIdx.x;
    if (i < NE) { g_counts[i] = 0; g_cursor[i] = 0; }
}

__global__ void rmsnorm_kernel(const float* __restrict__ in,
                               const float* __restrict__ w,
                               float* __restrict__ out) {
    int t = blockIdx.x;
    const float* row = in + (size_t)t*Dm;
    float ss = 0.f;
    for (int i = threadIdx.x; i < Dm; i += 256) { float v = row[i]; ss += v*v; }
    __shared__ float red[8];
    for (int o = 16; o; o >>= 1) ss += __shfl_xor_sync(0xffffffffu, ss, o);
    if ((threadIdx.x & 31) == 0) red[threadIdx.x >> 5] = ss;
    __syncthreads();
    float tot = 0.f;
    #pragma unroll
    for (int i = 0; i < 8; i++) tot += red[i];
    float inv = rsqrtf(tot * (1.f/(float)Dm) + 1e-5f);
    for (int i = threadIdx.x; i < Dm; i += 256)
        out[(size_t)t*Dm + i] = row[i] * inv * w[i];
}

// ---------------- tf32 tensor-core GEMM ----------------
// C[M,N] = A[M,K] @ B[K,N] (+addsrc). Block 128x128x32, 8 warps, warp 64x32.
// mode 0: plain (z==1 selects B2/C2). mode 1: MoE gather (A rows = g_h[slot_token]).
// mode 2: MoE contiguous grouped (A rows = A[(off+row)*K]).
__device__ __forceinline__ unsigned f2tf(float x) {
    unsigned r; asm("cvt.rna.tf32.f32 %0, %1;" : "=r"(r) : "f"(x)); return r;
}

__global__ void __launch_bounds__(256, 2) tf32_gemm(
    const float* __restrict__ A, const float* __restrict__ B,
    float* __restrict__ C, int M, int N, int K,
    const float* __restrict__ addsrc, int mode,
    const float* __restrict__ B2, float* __restrict__ C2)
{
    __shared__ unsigned As[128*36];
    __shared__ unsigned Bs[32*136];
    int cnt, off;
    if (mode == 0) {
        cnt = M; off = 0;
        if (blockIdx.z == 1) { B = B2; C = C2; }
    } else {
        int e = blockIdx.z;
        cnt = g_counts[e]; off = g_offsets[e];
        B += (size_t)e * K * N;
    }
    int bm = blockIdx.y * 128;
    if (bm >= cnt) return;
    int bn = blockIdx.x * 128;
    int tid = threadIdx.x;
    int lane = tid & 31, wid = tid >> 5;
    int warp_m = wid >> 2, warp_n = wid & 3;
    int lq = lane >> 2, lr = lane & 3;

    const float* aptr[4];
    bool aval[4];
    #pragma unroll
    for (int r = 0; r < 4; r++) {
        int m = r*32 + (tid >> 3);
        int row = bm + m;
        aval[r] = row < cnt;
        aptr[r] = A;
        if (aval[r]) {
            if (mode == 1)      aptr[r] = g_h + (size_t)g_slot_token[off + row] * K;
            else if (mode == 2) aptr[r] = A + (size_t)(off + row) * K;
            else                aptr[r] = A + (size_t)row * K;
        }
    }
    int ak4 = (tid & 7) * 4;
    int bk  = tid >> 5;
    int bn4 = lane * 4;

    float acc[4][4][4];
    #pragma unroll
    for (int i=0;i<4;i++)
        #pragma unroll
        for(int j=0;j<4;j++)
            #pragma unroll
            for(int c=0;c<4;c++) acc[i][j][c]=0.f;

    for (int k0 = 0; k0 < K; k0 += 32) {
        #pragma unroll
        for (int r = 0; r < 4; r++) {
            float4 av = make_float4(0.f,0.f,0.f,0.f);
            if (aval[r]) av = *(const float4*)(aptr[r] + k0 + ak4);
            int m = r*32 + (tid>>3);
            unsigned* dst = &As[m*36 + ak4];
            dst[0]=f2tf(av.x); dst[1]=f2tf(av.y); dst[2]=f2tf(av.z); dst[3]=f2tf(av.w);
        }
        #pragma unroll
        for (int r = 0; r < 4; r++) {
            int k = r*8 + bk;
            float4 bv = *(const float4*)(B + (size_t)(k0+k)*N + bn + bn4);
            uint4 u;
            u.x=f2tf(bv.x); u.y=f2tf(bv.y); u.z=f2tf(bv.z); u.w=f2tf(bv.w);
            *(uint4*)&Bs[k*136 + bn4] = u;
        }
        __syncthreads();
        #pragma unroll
        for (int ks = 0; ks < 4; ks++) {
            int k8 = ks*8;
            unsigned af[4][4], bf[4][2];
            #pragma unroll
            for (int mt=0; mt<4; mt++) {
                int m0 = warp_m*64 + mt*16;
                const unsigned* p = &As[(m0+lq)*36 + k8 + lr];
                af[mt][0] = p[0];
                af[mt][1] = p[8*36];
                af[mt][2] = p[4];
                af[mt][3] = p[8*36+4];
            }
            #pragma unroll
            for (int nt=0; nt<4; nt++) {
                int n0 = warp_n*32 + nt*8 + lq;
                bf[nt][0] = Bs[(k8+lr)*136 + n0];
                bf[nt][1] = Bs[(k8+4+lr)*136 + n0];
            }
            #pragma unroll
            for (int mt=0; mt<4; mt++)
                #pragma unroll
                for (int nt=0; nt<4; nt++) {
                    asm volatile(
                        "mma.sync.aligned.m16n8k8.row.col.f32.tf32.tf32.f32 "
                        "{%0,%1,%2,%3}, {%4,%5,%6,%7}, {%8,%9}, {%0,%1,%2,%3};"
                        : "+f"(acc[mt][nt][0]), "+f"(acc[mt][nt][1]),
                          "+f"(acc[mt][nt][2]), "+f"(acc[mt][nt][3])
                        : "r"(af[mt][0]), "r"(af[mt][1]), "r"(af[mt][2]), "r"(af[mt][3]),
                          "r"(bf[nt][0]), "r"(bf[nt][1]));
                }
        }
        __syncthreads();
    }
    #pragma unroll
    for (int mt=0; mt<4; mt++) {
        int row0 = bm + warp_m*64 + mt*16 + lq;
        #pragma unroll
        for (int half=0; half<2; half++) {
            int row = row0 + half*8;
            if (row >= cnt) continue;
            size_t crow = (size_t)(off + row);
            #pragma unroll
            for (int nt=0; nt<4; nt++) {
                int col = bn + warp_n*32 + nt*8 + 2*lr;
                float2 v;
                v.x = acc[mt][nt][half*2+0];
                v.y = acc[mt][nt][half*2+1];
                if (addsrc) {
                    float2 s = *(const float2*)(addsrc + crow*N + col);
                    v.x += s.x; v.y += s.y;
                }
                *(float2*)(C + crow*N + col) = v;
            }
        }
    }
}

// ---------------- RoPE ----------------
__global__ void rope_kernel() {
    int idx = blockIdx.x*256 + threadIdx.x;
    const int totq = Ttok*NH*(HDv/2);
    const int tot  = totq + Ttok*KVHv*(HDv/2);
    if (idx >= tot) return;
    float* base; int t, i;
    if (idx < totq) {
        i = idx & 63;
        int hh = (idx >> 6) & (NH-1);
        t = idx >> 10;
        base = g_q + (size_t)t*Dm + hh*HDv + 2*i;
    } else {
        int id2 = idx - totq;
        i = id2 & 63;
        int hh = (id2 >> 6) & (KVHv-1);
        t = id2 >> 8;
        base = g_k + (size_t)t*KVD + hh*HDv + 2*i;
    }
    int pos = t & (Lq-1);
    float inv = exp2f(-(float)i * (13.287712379549449f/64.f));
    float ang = (float)pos * inv;
    float c = cosf(ang), s = sinf(ang);
    float xr = base[0], xi = base[1];
    base[0] = xr*c - xi*s;
    base[1] = xr*s + xi*c;
}

// ---------------- flash attention (fp32, warp per query) ----------------
#define KT 32
__global__ void attn_kernel() {
    __shared__ float Ks[KT][HDv];
    __shared__ float Vs[KT][HDv];
    int b = blockIdx.z, h = blockIdx.y;
    int warp = threadIdx.x >> 5, lane = threadIdx.x & 31;
    int l = blockIdx.x * 8 + warp;
    int t = b * Lq + l;
    int kvh = h >> 2;
    const float scale = 0.08838834764831845f;
    float4 qv = *(const float4*)(g_q + (size_t)t*Dm + h*HDv + lane*4);
    qv.x *= scale; qv.y *= scale; qv.z *= scale; qv.w *= scale;
    float m = -1e30f, lsum = 0.f;
    float acc0 = 0.f, acc1 = 0.f, acc2 = 0.f, acc3 = 0.f;
    int maxl = blockIdx.x*8 + 7;
    int ntiles = maxl / KT + 1;
    for (int kt = 0; kt < ntiles; kt++) {
        int base = kt * KT;
        for (int idx = threadIdx.x; idx < KT*HDv/4; idx += 256) {
            int row = idx >> 5;
            int col = (idx & 31) * 4;
            size_t goff = (size_t)(b*Lq + base + row)*KVD + kvh*HDv + col;
            *(float4*)&Ks[row][col] = *(const float4*)(g_k + goff);
            *(float4*)&Vs[row][col] = *(const float4*)(g_v + goff);
        }
        __syncthreads();
        int jmax = min(KT, l - base + 1);
        for (int j = 0; j < jmax; j++) {
            float4 kv4 = *(const float4*)&Ks[j][lane*4];
            float s = qv.x*kv4.x + qv.y*kv4.y + qv.z*kv4.z + qv.w*kv4.w;
            s += __shfl_xor_sync(0xffffffffu, s, 16);
            s += __shfl_xor_sync(0xffffffffu, s, 8);
            s += __shfl_xor_sync(0xffffffffu, s, 4);
            s += __shfl_xor_sync(0xffffffffu, s, 2);
            s += __shfl_xor_sync(0xffffffffu, s, 1);
            float mn = fmaxf(m, s);
            float alpha = __expf(m - mn);
            float p = __expf(s - mn);
            lsum = lsum*alpha + p;
            float4 vv = *(const float4*)&Vs[j][lane*4];
            acc0 = acc0*alpha + p*vv.x;
            acc1 = acc1*alpha + p*vv.y;
            acc2 = acc2*alpha + p*vv.z;
            acc3 = acc3*alpha + p*vv.w;
            m = mn;
        }
        __syncthreads();
    }
    float inv = 1.f / lsum;
    float4 o = make_float4(acc0*inv, acc1*inv, acc2*inv, acc3*inv);
    *(float4*)(g_ao + (size_t)t*Dm + h*HDv + lane*4) = o;
}

// ---------------- gating ----------------
__global__ void gate_kernel(const float* __restrict__ gw) {
    int t = blockIdx.x;
    int warp = threadIdx.x >> 5, lane = threadIdx.x & 31;
    const float* row = g_h + (size_t)t*Dm;
    float s = 0.f;
    for (int i = lane; i < Dm; i += 32) s += row[i] * gw[(size_t)i*NE + warp];
    for (int o = 16; o; o >>= 1) s += __shfl_xor_sync(0xffffffffu, s, o);
    __shared__ float logits[NE];
    if (lane == 0) logits[warp] = s;
    __syncthreads();
    if (threadIdx.x == 0) {
        float mx = logits[0];
        for (int e = 1; e < NE; e++) mx = fmaxf(mx, logits[e]);
        float ex[NE]; float sum = 0.f;
        for (int e = 0; e < NE; e++) { ex[e] = expf(logits[e]-mx); sum += ex[e]; }
        float invs = 1.f/sum;
        float sc[NE];
        for (int e = 0; e < NE; e++) { sc[e] = ex[e]*invs; g_scores[t*NE+e] = sc[e]; }
        int e0 = 0; float m0 = sc[0];
        for (int e = 1; e < NE; e++) if (sc[e] > m0) { m0 = sc[e]; e0 = e; }
        int e1 = -1; float m1 = -1.f;
        for (int e = 0; e < NE; e++) if (e != e0 && sc[e] > m1) { m1 = sc[e]; e1 = e; }
        float wsum = m0 + m1;
        g_top_idx[t*2]   = e0;  g_top_idx[t*2+1] = e1;
        g_top_w[t*2]     = m0/wsum;
        g_top_w[t*2+1]   = m1/wsum;
        atomicAdd(&g_counts[e0], 1);
        atomicAdd(&g_counts[e1], 1);
    }
}

__global__ void finalize_gate_kernel(float* aux_out) {
    int warp = threadIdx.x >> 5, lane = threadIdx.x & 31;
    float s = 0.f;
    for (int t = lane; t < Ttok; t += 32) s += g_scores[t*NE + warp];
    for (int o = 16; o; o >>= 1) s += __shfl_xor_sync(0xffffffffu, s, o);
    __shared__ float ps[NE];
    if (lane == 0) ps[warp] = s;
    __syncthreads();
    if (threadIdx.x == 0) {
        int off = 0; float aux = 0.f;
        for (int e = 0; e < NE; e++) {
            g_offsets[e] = off; off += g_counts[e];
            float f = (float)g_counts[e] / (float)Ttok;
            float p = ps[e] / (float)Ttok;
            aux += f * p;
        }
        g_offsets[NE] = off;
        aux_out[0] = 0.01f * (float)NE * aux;
    }
}

__global__ void scatter_kernel() {
    int t = blockIdx.x*256 + threadIdx.x;
    if (t >= Ttok) return;
    for (int j = 0; j < 2; j++) {
        int e = g_top_idx[t*2+j];
        int pos = atomicAdd(&g_cursor[e], 1);
        int slot = g_offsets[e] + pos;
        g_slot_token[slot] = t;
        g_slot_w[slot] = g_top_w[t*2+j];
        g_slot_of[t*2+j] = slot;
    }
}

// ---------------- silu(g)*u in-place into g_g ----------------
__global__ void silu_mul_kernel() {
    size_t i = ((size_t)blockIdx.x*256 + threadIdx.x)*4;
    float4 g = *(float4*)(g_g + i);
    float4 u = *(float4*)(g_u + i);
    g.x = g.x / (1.f + __expf(-g.x)) * u.x;
    g.y = g.y / (1.f + __expf(-g.y)) * u.y;
    g.z = g.z / (1.f + __expf(-g.z)) * u.z;
    g.w = g.w / (1.f + __expf(-g.w)) * u.w;
    *(float4*)(g_g + i) = g;
}

__global__ void final_add_kernel(float* __restrict__ out) {
    int t = blockIdx.x;
    int s0 = g_slot_of[t*2], s1 = g_slot_of[t*2+1];
    float w0 = g_slot_w[s0], w1 = g_slot_w[s1];
    for (int i = threadIdx.x*4; i < Dm; i += 256*4) {
        float4 a  = *(float4*)(out + (size_t)t*Dm + i);
        float4 y0 = *(const float4*)(g_y + (size_t)s0*Dm + i);
        float4 y1 = *(const float4*)(g_y + (size_t)s1*Dm + i);
        a.x += w0*y0.x + w1*y1.x;
        a.y += w0*y0.y + w1*y1.y;
        a.z += w0*y0.z + w1*y1.z;
        a.w += w0*y0.w + w1*y1.w;
        *(float4*)(out + (size_t)t*Dm + i) = a;
    }
}

// ---------------- launch ----------------
extern "C" void kernel_launch(void* const* d_in, const int* in_sizes, int n_in,
                              void* d_out, int out_size) {
    const float* x           = (const float*)d_in[0];
    const float* w_q         = (const float*)d_in[1];
    const float* w_k         = (const float*)d_in[2];
    const float* w_v         = (const float*)d_in[3];
    const float* w_o         = (const float*)d_in[4];
    const float* attn_norm_w = (const float*)d_in[5];
    const float* moe_norm_w  = (const float*)d_in[6];
    const float* gate_w      = (const float*)d_in[7];
    const float* w1          = (const float*)d_in[8];
    const float* w3          = (const float*)d_in[9];
    const float* w2          = (const float*)d_in[10];
    float* out = (float*)d_out;

    float *ph, *pq, *pk, *pv, *pao, *pg, *pu, *py;
    cudaGetSymbolAddress((void**)&ph,  g_h);
    cudaGetSymbolAddress((void**)&pq,  g_q);
    cudaGetSymbolAddress((void**)&pk,  g_k);
    cudaGetSymbolAddress((void**)&pv,  g_v);
    cudaGetSymbolAddress((void**)&pao, g_ao);
    cudaGetSymbolAddress((void**)&pg,  g_g);
    cudaGetSymbolAddress((void**)&pu,  g_u);
    cudaGetSymbolAddress((void**)&py,  g_y);

    zero_kernel<<<1, 32>>>();
    rmsnorm_kernel<<<Ttok, 256>>>(x, attn_norm_w, ph);
    // Q projection
    tf32_gemm<<<dim3(Dm/128, Ttok/128, 1), 256>>>(ph, w_q, pq, Ttok, Dm, Dm,
                                                  nullptr, 0, nullptr, nullptr);
    // K and V projections fused via z
    tf32_gemm<<<dim3(KVD/128, Ttok/128, 2), 256>>>(ph, w_k, pk, Ttok, KVD, Dm,
                                                   nullptr, 0, w_v, pv);
    {
        int tot = Ttok*NH*(HDv/2) + Ttok*KVHv*(HDv/2);
        rope_kernel<<<(tot + 255)/256, 256>>>();
    }
    attn_kernel<<<dim3(Lq/8, NH, Bq), 256>>>();
    // O projection + residual
    tf32_gemm<<<dim3(Dm/128, Ttok/128, 1), 256>>>(pao, w_o, out, Ttok, Dm, Dm,
                                                  x, 0, nullptr, nullptr);
    rmsnorm_kernel<<<Ttok, 256>>>(out, moe_norm_w, ph);
    gate_kernel<<<Ttok, 256>>>(gate_w);
    finalize_gate_kernel<<<1, 256>>>(out + (size_t)Ttok*Dm);
    scatter_kernel<<<(Ttok + 255)/256, 256>>>();
    // MoE: g = Xg @ w1, u = Xg @ w3 (gathered rows)
    tf32_gemm<<<dim3(NI/128, SLOTS/128, NE), 256>>>(nullptr, w1, pg, 0, NI, Dm,
                                                    nullptr, 1, nullptr, nullptr);
    tf32_gemm<<<dim3(NI/128, SLOTS/128, NE), 256>>>(nullptr, w3, pu, 0, NI, Dm,
                                                    nullptr, 1, nullptr, nullptr);
    silu_mul_kernel<<<SLOTS*NI/1024, 256>>>();
    // MoE down-proj: y = act @ w2 (contiguous grouped)
    tf32_gemm<<<dim3(Dm/128, SLOTS/128, NE), 256>>>(pg, w2, py, 0, Dm, NI,
                                                    nullptr, 2, nullptr, nullptr);
    final_add_kernel<<<Ttok, 256>>>(out);
}

// round 3
// speedup vs baseline: 4.3645x; 2.5217x over previous
#include <cuda_runtime.h>
#include <math.h>

#define Bq 2
#define Lq 2048
#define Dm 2048
#define NH 16
#define HDv 128
#define KVHv 4
#define NE 8
#define NI 1024
#define Ttok (Bq*Lq)          /* 4096 */
#define KVD (KVHv*HDv)        /* 512  */
#define SLOTS (Ttok*2)        /* 8192 */

// ---------------- scratch ----------------
__device__ float g_h[Ttok*Dm];
__device__ float g_q[Ttok*Dm];
__device__ float g_k[Ttok*KVD];
__device__ float g_v[Ttok*KVD];
__device__ float g_ao[Ttok*Dm];
__device__ float g_g[SLOTS*NI];
__device__ float g_u[SLOTS*NI];
__device__ float g_y[SLOTS*Dm];
__device__ float g_scores[Ttok*NE];
__device__ int   g_counts[NE];
__device__ int   g_offsets[NE+1];
__device__ int   g_cursor[NE];
__device__ int   g_top_idx[Ttok*2];
__device__ float g_top_w[Ttok*2];
__device__ int   g_slot_token[SLOTS];
__device__ float g_slot_w[SLOTS];
__device__ int   g_slot_of[Ttok*2];

__device__ __forceinline__ unsigned f2tf(float x) {
    unsigned r; asm("cvt.rna.tf32.f32 %0, %1;" : "=r"(r) : "f"(x)); return r;
}

// ---------------- small kernels ----------------
__global__ void zero_kernel() {
    int i = threadIdx.x;
    if (i < NE) { g_counts[i] = 0; g_cursor[i] = 0; }
}

__global__ void rmsnorm_kernel(const float* __restrict__ in,
                               const float* __restrict__ w,
                               float* __restrict__ out) {
    int t = blockIdx.x;
    const float* row = in + (size_t)t*Dm;
    float ss = 0.f;
    for (int i = threadIdx.x; i < Dm; i += 256) { float v = row[i]; ss += v*v; }
    __shared__ float red[8];
    for (int o = 16; o; o >>= 1) ss += __shfl_xor_sync(0xffffffffu, ss, o);
    if ((threadIdx.x & 31) == 0) red[threadIdx.x >> 5] = ss;
    __syncthreads();
    float tot = 0.f;
    #pragma unroll
    for (int i = 0; i < 8; i++) tot += red[i];
    float inv = rsqrtf(tot * (1.f/(float)Dm) + 1e-5f);
    for (int i = threadIdx.x; i < Dm; i += 256)
        out[(size_t)t*Dm + i] = row[i] * inv * w[i];
}

// ---------------- tf32 tensor-core GEMM ----------------
__global__ void __launch_bounds__(256, 2) tf32_gemm(
    const float* __restrict__ A, const float* __restrict__ B,
    float* __restrict__ C, int M, int N, int K,
    const float* __restrict__ addsrc, int mode,
    const float* __restrict__ B2, float* __restrict__ C2)
{
    __shared__ unsigned As[128*36];
    __shared__ unsigned Bs[32*136];
    int cnt, off;
    if (mode == 0) {
        cnt = M; off = 0;
        if (blockIdx.z == 1) { B = B2; C = C2; }
    } else {
        int e = blockIdx.z;
        cnt = g_counts[e]; off = g_offsets[e];
        B += (size_t)e * K * N;
    }
    int bm = blockIdx.y * 128;
    if (bm >= cnt) return;
    int bn = blockIdx.x * 128;
    int tid = threadIdx.x;
    int lane = tid & 31, wid = tid >> 5;
    int warp_m = wid >> 2, warp_n = wid & 3;
    int lq = lane >> 2, lr = lane & 3;

    const float* aptr[4];
    bool aval[4];
    #pragma unroll
    for (int r = 0; r < 4; r++) {
        int m = r*32 + (tid >> 3);
        int row = bm + m;
        aval[r] = row < cnt;
        aptr[r] = A;
        if (aval[r]) {
            if (mode == 1)      aptr[r] = g_h + (size_t)g_slot_token[off + row] * K;
            else if (mode == 2) aptr[r] = A + (size_t)(off + row) * K;
            else                aptr[r] = A + (size_t)row * K;
        }
    }
    int ak4 = (tid & 7) * 4;
    int bk  = tid >> 5;
    int bn4 = lane * 4;

    float acc[4][4][4];
    #pragma unroll
    for (int i=0;i<4;i++)
        #pragma unroll
        for(int j=0;j<4;j++)
            #pragma unroll
            for(int c=0;c<4;c++) acc[i][j][c]=0.f;

    for (int k0 = 0; k0 < K; k0 += 32) {
        #pragma unroll
        for (int r = 0; r < 4; r++) {
            float4 av = make_float4(0.f,0.f,0.f,0.f);
            if (aval[r]) av = *(const float4*)(aptr[r] + k0 + ak4);
            int m = r*32 + (tid>>3);
            unsigned* dst = &As[m*36 + ak4];
            dst[0]=f2tf(av.x); dst[1]=f2tf(av.y); dst[2]=f2tf(av.z); dst[3]=f2tf(av.w);
        }
        #pragma unroll
        for (int r = 0; r < 4; r++) {
            int k = r*8 + bk;
            float4 bv = *(const float4*)(B + (size_t)(k0+k)*N + bn + bn4);
            uint4 u;
            u.x=f2tf(bv.x); u.y=f2tf(bv.y); u.z=f2tf(bv.z); u.w=f2tf(bv.w);
            *(uint4*)&Bs[k*136 + bn4] = u;
        }
        __syncthreads();
        #pragma unroll
        for (int ks = 0; ks < 4; ks++) {
            int k8 = ks*8;
            unsigned af[4][4], bf[4][2];
            #pragma unroll
            for (int mt=0; mt<4; mt++) {
                int m0 = warp_m*64 + mt*16;
                const unsigned* p = &As[(m0+lq)*36 + k8 + lr];
                af[mt][0] = p[0];
                af[mt][1] = p[8*36];
                af[mt][2] = p[4];
                af[mt][3] = p[8*36+4];
            }
            #pragma unroll
            for (int nt=0; nt<4; nt++) {
                int n0 = warp_n*32 + nt*8 + lq;
                bf[nt][0] = Bs[(k8+lr)*136 + n0];
                bf[nt][1] = Bs[(k8+4+lr)*136 + n0];
            }
            #pragma unroll
            for (int mt=0; mt<4; mt++)
                #pragma unroll
                for (int nt=0; nt<4; nt++) {
                    asm volatile(
                        "mma.sync.aligned.m16n8k8.row.col.f32.tf32.tf32.f32 "
                        "{%0,%1,%2,%3}, {%4,%5,%6,%7}, {%8,%9}, {%0,%1,%2,%3};"
                        : "+f"(acc[mt][nt][0]), "+f"(acc[mt][nt][1]),
                          "+f"(acc[mt][nt][2]), "+f"(acc[mt][nt][3])
                        : "r"(af[mt][0]), "r"(af[mt][1]), "r"(af[mt][2]), "r"(af[mt][3]),
                          "r"(bf[nt][0]), "r"(bf[nt][1]));
                }
        }
        __syncthreads();
    }
    #pragma unroll
    for (int mt=0; mt<4; mt++) {
        int row0 = bm + warp_m*64 + mt*16 + lq;
        #pragma unroll
        for (int half=0; half<2; half++) {
            int row = row0 + half*8;
            if (row >= cnt) continue;
            size_t crow = (size_t)(off + row);
            #pragma unroll
            for (int nt=0; nt<4; nt++) {
                int col = bn + warp_n*32 + nt*8 + 2*lr;
                float2 v;
                v.x = acc[mt][nt][half*2+0];
                v.y = acc[mt][nt][half*2+1];
                if (addsrc) {
                    float2 s = *(const float2*)(addsrc + crow*N + col);
                    v.x += s.x; v.y += s.y;
                }
                *(float2*)(C + crow*N + col) = v;
            }
        }
    }
}

// ---------------- RoPE ----------------
__global__ void rope_kernel() {
    int idx = blockIdx.x*256 + threadIdx.x;
    const int totq = Ttok*NH*(HDv/2);
    const int tot  = totq + Ttok*KVHv*(HDv/2);
    if (idx >= tot) return;
    float* base; int t, i;
    if (idx < totq) {
        i = idx & 63;
        int hh = (idx >> 6) & (NH-1);
        t = idx >> 10;
        base = g_q + (size_t)t*Dm + hh*HDv + 2*i;
    } else {
        int id2 = idx - totq;
        i = id2 & 63;
        int hh = (id2 >> 6) & (KVHv-1);
        t = id2 >> 8;
        base = g_k + (size_t)t*KVD + hh*HDv + 2*i;
    }
    int pos = t & (Lq-1);
    float inv = exp2f(-(float)i * (13.287712379549449f/64.f));
    float ang = (float)pos * inv;
    float c = cosf(ang), s = sinf(ang);
    float xr = base[0], xi = base[1];
    base[0] = xr*c - xi*s;
    base[1] = xr*s + xi*c;
}

// ---------------- tensor-core flash attention ----------------
// block = (q-tile 64, head, batch), 128 threads (4 warps, 16 q-rows each).
// KT=32 key tile. smem (floats): Q[64][132] K[32][132] V[32][136] P[64][36].
#define QPAD 132
#define VPAD 136
#define PPAD 36
#define AT_QS 0
#define AT_KS (64*QPAD)                 /* 8448  */
#define AT_VS (AT_KS + 32*QPAD)         /* 12672 */
#define AT_PS (AT_VS + 32*VPAD)         /* 17024 */
#define AT_SMEM_WORDS (AT_PS + 64*PPAD) /* 19328 */

__global__ void __launch_bounds__(128) attn_mma_kernel() {
    extern __shared__ unsigned sm[];
    int b = blockIdx.z, h = blockIdx.y;
    int q0 = blockIdx.x * 64;
    int kvh = h >> 2;
    int tid = threadIdx.x;
    int lane = tid & 31, w = tid >> 5;
    int lq = lane >> 2, lr = lane & 3;
    const float scale = 0.08838834764831845f;

    // load Q tile (scaled, tf32)
    for (int idx = tid; idx < 64*32; idx += 128) {
        int row = idx >> 5, c4 = (idx & 31) * 4;
        float4 qv = *(const float4*)(g_q + (size_t)(b*Lq + q0 + row)*Dm + h*HDv + c4);
        unsigned* dst = &sm[AT_QS + row*QPAD + c4];
        dst[0]=f2tf(qv.x*scale); dst[1]=f2tf(qv.y*scale);
        dst[2]=f2tf(qv.z*scale); dst[3]=f2tf(qv.w*scale);
    }

    float o[16][4];
    #pragma unroll
    for (int nt=0;nt<16;nt++){o[nt][0]=0.f;o[nt][1]=0.f;o[nt][2]=0.f;o[nt][3]=0.f;}
    float m0 = -1e30f, m1 = -1e30f, l0 = 0.f, l1 = 0.f;
    int row_base = q0 + w*16;
    int ntiles = (q0 + 64) / 32;
    __syncthreads();

    for (int kt = 0; kt < ntiles; kt++) {
        int base = kt * 32;
        // load K,V tiles
        for (int idx = tid; idx < 32*32; idx += 128) {
            int row = idx >> 5, c4 = (idx & 31) * 4;
            size_t goff = (size_t)(b*Lq + base + row)*KVD + kvh*HDv + c4;
            float4 kv = *(const float4*)(g_k + goff);
            unsigned* kd = &sm[AT_KS + row*QPAD + c4];
            kd[0]=f2tf(kv.x); kd[1]=f2tf(kv.y); kd[2]=f2tf(kv.z); kd[3]=f2tf(kv.w);
            float4 vv = *(const float4*)(g_v + goff);
            unsigned* vd = &sm[AT_VS + row*VPAD + c4];
            vd[0]=f2tf(vv.x); vd[1]=f2tf(vv.y); vd[2]=f2tf(vv.z); vd[3]=f2tf(vv.w);
        }
        __syncthreads();

        // S = Q K^T  (warp: 16 x 32)
        float s[4][4];
        #pragma unroll
        for (int nt=0;nt<4;nt++){s[nt][0]=0.f;s[nt][1]=0.f;s[nt][2]=0.f;s[nt][3]=0.f;}
        #pragma unroll
        for (int ks = 0; ks < 16; ks++) {
            int k8 = ks*8;
            unsigned a0,a1,a2,a3;
            const unsigned* qp = &sm[AT_QS + (w*16+lq)*QPAD + k8 + lr];
            a0 = qp[0]; a1 = qp[8*QPAD]; a2 = qp[4]; a3 = qp[8*QPAD+4];
            #pragma unroll
            for (int nt=0; nt<4; nt++) {
                unsigned b0 = sm[AT_KS + (nt*8+lq)*QPAD + k8 + lr];
                unsigned b1 = sm[AT_KS + (nt*8+lq)*QPAD + k8 + lr + 4];
                asm volatile(
                    "mma.sync.aligned.m16n8k8.row.col.f32.tf32.tf32.f32 "
                    "{%0,%1,%2,%3}, {%4,%5,%6,%7}, {%8,%9}, {%0,%1,%2,%3};"
                    : "+f"(s[nt][0]), "+f"(s[nt][1]), "+f"(s[nt][2]), "+f"(s[nt][3])
                    : "r"(a0), "r"(a1), "r"(a2), "r"(a3), "r"(b0), "r"(b1));
            }
        }

        // causal mask (only diagonal-overlapping tiles)
        if (base + 31 > row_base) {
            int i0 = row_base + lq, i1 = row_base + lq + 8;
            #pragma unroll
            for (int nt=0; nt<4; nt++) {
                int j = base + nt*8 + 2*lr;
                if (j   > i0) s[nt][0] = -1e30f;
                if (j+1 > i0) s[nt][1] = -1e30f;
                if (j   > i1) s[nt][2] = -1e30f;
                if (j+1 > i1) s[nt][3] = -1e30f;
            }
        }

        // online softmax
        float mx0 = -1e30f, mx1 = -1e30f;
        #pragma unroll
        for (int nt=0; nt<4; nt++) {
            mx0 = fmaxf(mx0, fmaxf(s[nt][0], s[nt][1]));
            mx1 = fmaxf(mx1, fmaxf(s[nt][2], s[nt][3]));
        }
        mx0 = fmaxf(mx0, __shfl_xor_sync(0xffffffffu, mx0, 1));
        mx0 = fmaxf(mx0, __shfl_xor_sync(0xffffffffu, mx0, 2));
        mx1 = fmaxf(mx1, __shfl_xor_sync(0xffffffffu, mx1, 1));
        mx1 = fmaxf(mx1, __shfl_xor_sync(0xffffffffu, mx1, 2));
        float mn0 = fmaxf(m0, mx0), mn1 = fmaxf(m1, mx1);
        float al0 = __expf(m0 - mn0), al1 = __expf(m1 - mn1);
        float rs0 = 0.f, rs1 = 0.f;
        #pragma unroll
        for (int nt=0; nt<4; nt++) {
            s[nt][0] = __expf(s[nt][0] - mn0);
            s[nt][1] = __expf(s[nt][1] - mn0);
            s[nt][2] = __expf(s[nt][2] - mn1);
            s[nt][3] = __expf(s[nt][3] - mn1);
            rs0 += s[nt][0] + s[nt][1];
            rs1 += s[nt][2] + s[nt][3];
        }
        rs0 += __shfl_xor_sync(0xffffffffu, rs0, 1);
        rs0 += __shfl_xor_sync(0xffffffffu, rs0, 2);
        rs1 += __shfl_xor_sync(0xffffffffu, rs1, 1);
        rs1 += __shfl_xor_sync(0xffffffffu, rs1, 2);
        l0 = l0*al0 + rs0;
        l1 = l1*al1 + rs1;
        m0 = mn0; m1 = mn1;
        #pragma unroll
        for (int nt=0; nt<16; nt++) {
            o[nt][0]*=al0; o[nt][1]*=al0; o[nt][2]*=al1; o[nt][3]*=al1;
        }

        // stage P (tf32) into per-warp smem
        #pragma unroll
        for (int nt=0; nt<4; nt++) {
            unsigned* p0 = &sm[AT_PS + (w*16+lq)*PPAD + nt*8 + 2*lr];
            p0[0] = f2tf(s[nt][0]); p0[1] = f2tf(s[nt][1]);
            unsigned* p1 = &sm[AT_PS + (w*16+lq+8)*PPAD + nt*8 + 2*lr];
            p1[0] = f2tf(s[nt][2]); p1[1] = f2tf(s[nt][3]);
        }
        __syncwarp();

        // O += P V  (A = P[16,32], B = V[32,128])
        #pragma unroll
        for (int ks = 0; ks < 4; ks++) {
            int k8 = ks*8;
            const unsigned* pp = &sm[AT_PS + (w*16+lq)*PPAD + k8 + lr];
            unsigned a0 = pp[0], a1 = pp[8*PPAD], a2 = pp[4], a3 = pp[8*PPAD+4];
            #pragma unroll
            for (int nt=0; nt<16; nt++) {
                unsigned b0 = sm[AT_VS + (k8+lr)*VPAD + nt*8 + lq];
                unsigned b1 = sm[AT_VS + (k8+lr+4)*VPAD + nt*8 + lq];
                asm volatile(
                    "mma.sync.aligned.m16n8k8.row.col.f32.tf32.tf32.f32 "
                    "{%0,%1,%2,%3}, {%4,%5,%6,%7}, {%8,%9}, {%0,%1,%2,%3};"
                    : "+f"(o[nt][0]), "+f"(o[nt][1]), "+f"(o[nt][2]), "+f"(o[nt][3])
                    : "r"(a0), "r"(a1), "r"(a2), "r"(a3), "r"(b0), "r"(b1));
            }
        }
        __syncthreads();
    }

    float inv0 = 1.f / l0, inv1 = 1.f / l1;
    int t0 = b*Lq + row_base + lq;
    #pragma unroll
    for (int nt=0; nt<16; nt++) {
        int col = h*HDv + nt*8 + 2*lr;
        float2 v0 = make_float2(o[nt][0]*inv0, o[nt][1]*inv0);
        float2 v1 = make_float2(o[nt][2]*inv1, o[nt][3]*inv1);
        *(float2*)(g_ao + (size_t)t0*Dm + col) = v0;
        *(float2*)(g_ao + (size_t)(t0+8)*Dm + col) = v1;
    }
}

// ---------------- gating ----------------
__global__ void gate_kernel(const float* __restrict__ gw) {
    int t = blockIdx.x;
    int warp = threadIdx.x >> 5, lane = threadIdx.x & 31;
    const float* row = g_h + (size_t)t*Dm;
    float s = 0.f;
    for (int i = lane; i < Dm; i += 32) s += row[i] * gw[(size_t)i*NE + warp];
    for (int o = 16; o; o >>= 1) s += __shfl_xor_sync(0xffffffffu, s, o);
    __shared__ float logits[NE];
    if (lane == 0) logits[warp] = s;
    __syncthreads();
    if (threadIdx.x == 0) {
        float mx = logits[0];
        for (int e = 1; e < NE; e++) mx = fmaxf(mx, logits[e]);
        float ex[NE]; float sum = 0.f;
        for (int e = 0; e < NE; e++) { ex[e] = expf(logits[e]-mx); sum += ex[e]; }
        float invs = 1.f/sum;
        float sc[NE];
        for (int e = 0; e < NE; e++) { sc[e] = ex[e]*invs; g_scores[t*NE+e] = sc[e]; }
        int e0 = 0; float m0 = sc[0];
        for (int e = 1; e < NE; e++) if (sc[e] > m0) { m0 = sc[e]; e0 = e; }
        int e1 = -1; float m1 = -1.f;
        for (int e = 0; e < NE; e++) if (e != e0 && sc[e] > m1) { m1 = sc[e]; e1 = e; }
        float wsum = m0 + m1;
        g_top_idx[t*2]   = e0;  g_top_idx[t*2+1] = e1;
        g_top_w[t*2]     = m0/wsum;
        g_top_w[t*2+1]   = m1/wsum;
        atomicAdd(&g_counts[e0], 1);
        atomicAdd(&g_counts[e1], 1);
    }
}

__global__ void finalize_gate_kernel(float* aux_out) {
    int warp = threadIdx.x >> 5, lane = threadIdx.x & 31;
    float s = 0.f;
    for (int t = lane; t < Ttok; t += 32) s += g_scores[t*NE + warp];
    for (int o = 16; o; o >>= 1) s += __shfl_xor_sync(0xffffffffu, s, o);
    __shared__ float ps[NE];
    if (lane == 0) ps[warp] = s;
    __syncthreads();
    if (threadIdx.x == 0) {
        int off = 0; float aux = 0.f;
        for (int e = 0; e < NE; e++) {
            g_offsets[e] = off; off += g_counts[e];
            float f = (float)g_counts[e] / (float)Ttok;
            float p = ps[e] / (float)Ttok;
            aux += f * p;
        }
        g_offsets[NE] = off;
        aux_out[0] = 0.01f * (float)NE * aux;
    }
}

__global__ void scatter_kernel() {
    int t = blockIdx.x*256 + threadIdx.x;
    if (t >= Ttok) return;
    for (int j = 0; j < 2; j++) {
        int e = g_top_idx[t*2+j];
        int pos = atomicAdd(&g_cursor[e], 1);
        int slot = g_offsets[e] + pos;
        g_slot_token[slot] = t;
        g_slot_w[slot] = g_top_w[t*2+j];
        g_slot_of[t*2+j] = slot;
    }
}

// ---------------- silu(g)*u ----------------
__global__ void silu_mul_kernel() {
    size_t i = ((size_t)blockIdx.x*256 + threadIdx.x)*4;
    float4 g = *(float4*)(g_g + i);
    float4 u = *(float4*)(g_u + i);
    g.x = g.x / (1.f + __expf(-g.x)) * u.x;
    g.y = g.y / (1.f + __expf(-g.y)) * u.y;
    g.z = g.z / (1.f + __expf(-g.z)) * u.z;
    g.w = g.w / (1.f + __expf(-g.w)) * u.w;
    *(float4*)(g_g + i) = g;
}

__global__ void final_add_kernel(float* __restrict__ out) {
    int t = blockIdx.x;
    int s0 = g_slot_of[t*2], s1 = g_slot_of[t*2+1];
    float w0 = g_slot_w[s0], w1 = g_slot_w[s1];
    for (int i = threadIdx.x*4; i < Dm; i += 256*4) {
        float4 a  = *(float4*)(out + (size_t)t*Dm + i);
        float4 y0 = *(const float4*)(g_y + (size_t)s0*Dm + i);
        float4 y1 = *(const float4*)(g_y + (size_t)s1*Dm + i);
        a.x += w0*y0.x + w1*y1.x;
        a.y += w0*y0.y + w1*y1.y;
        a.z += w0*y0.z + w1*y1.z;
        a.w += w0*y0.w + w1*y1.w;
        *(float4*)(out + (size_t)t*Dm + i) = a;
    }
}

// ---------------- launch ----------------
extern "C" void kernel_launch(void* const* d_in, const int* in_sizes, int n_in,
                              void* d_out, int out_size) {
    const float* x           = (const float*)d_in[0];
    const float* w_q         = (const float*)d_in[1];
    const float* w_k         = (const float*)d_in[2];
    const float* w_v         = (const float*)d_in[3];
    const float* w_o         = (const float*)d_in[4];
    const float* attn_norm_w = (const float*)d_in[5];
    const float* moe_norm_w  = (const float*)d_in[6];
    const float* gate_w      = (const float*)d_in[7];
    const float* w1          = (const float*)d_in[8];
    const float* w3          = (const float*)d_in[9];
    const float* w2          = (const float*)d_in[10];
    float* out = (float*)d_out;

    float *ph, *pq, *pk, *pv, *pao, *pg, *pu, *py;
    cudaGetSymbolAddress((void**)&ph,  g_h);
    cudaGetSymbolAddress((void**)&pq,  g_q);
    cudaGetSymbolAddress((void**)&pk,  g_k);
    cudaGetSymbolAddress((void**)&pv,  g_v);
    cudaGetSymbolAddress((void**)&pao, g_ao);
    cudaGetSymbolAddress((void**)&pg,  g_g);
    cudaGetSymbolAddress((void**)&pu,  g_u);
    cudaGetSymbolAddress((void**)&py,  g_y);

    static int smem_set = 0;
    const int attn_smem = AT_SMEM_WORDS * 4;
    if (!smem_set) {
        cudaFuncSetAttribute(attn_mma_kernel,
                             cudaFuncAttributeMaxDynamicSharedMemorySize, attn_smem);
        smem_set = 1;
    }

    zero_kernel<<<1, 32>>>();
    rmsnorm_kernel<<<Ttok, 256>>>(x, attn_norm_w, ph);
    tf32_gemm<<<dim3(Dm/128, Ttok/128, 1), 256>>>(ph, w_q, pq, Ttok, Dm, Dm,
                                                  nullptr, 0, nullptr, nullptr);
    tf32_gemm<<<dim3(KVD/128, Ttok/128, 2), 256>>>(ph, w_k, pk, Ttok, KVD, Dm,
                                                   nullptr, 0, w_v, pv);
    {
        int tot = Ttok*NH*(HDv/2) + Ttok*KVHv*(HDv/2);
        rope_kernel<<<(tot + 255)/256, 256>>>();
    }
    attn_mma_kernel<<<dim3(Lq/64, NH, Bq), 128, attn_smem>>>();
    tf32_gemm<<<dim3(Dm/128, Ttok/128, 1), 256>>>(pao, w_o, out, Ttok, Dm, Dm,
                                                  x, 0, nullptr, nullptr);
    rmsnorm_kernel<<<Ttok, 256>>>(out, moe_norm_w, ph);
    gate_kernel<<<Ttok, 256>>>(gate_w);
    finalize_gate_kernel<<<1, 256>>>(out + (size_t)Ttok*Dm);
    scatter_kernel<<<(Ttok + 255)/256, 256>>>();
    tf32_gemm<<<dim3(NI/128, SLOTS/128, NE), 256>>>(nullptr, w1, pg, 0, NI, Dm,
                                                    nullptr, 1, nullptr, nullptr);
    tf32_gemm<<<dim3(NI/128, SLOTS/128, NE), 256>>>(nullptr, w3, pu, 0, NI, Dm,
                                                    nullptr, 1, nullptr, nullptr);
    silu_mul_kernel<<<SLOTS*NI/1024, 256>>>();
    tf32_gemm<<<dim3(Dm/128, SLOTS/128, NE), 256>>>(pg, w2, py, 0, Dm, NI,
                                                    nullptr, 2, nullptr, nullptr);
    final_add_kernel<<<Ttok, 256>>>(out);
}

// round 5
// speedup vs baseline: 5.1591x; 1.1821x over previous
#include <cuda_runtime.h>
#include <math.h>

#define Bq 2
#define Lq 2048
#define Dm 2048
#define NH 16
#define HDv 128
#define KVHv 4
#define NE 8
#define NI 1024
#define Ttok (Bq*Lq)          /* 4096 */
#define KVD (KVHv*HDv)        /* 512  */
#define SLOTS (Ttok*2)        /* 8192 */

// ---------------- scratch ----------------
__device__ float g_h[Ttok*Dm];
__device__ float g_q[Ttok*Dm];
__device__ float g_k[Ttok*KVD];
__device__ float g_v[Ttok*KVD];
__device__ float g_ao[Ttok*Dm];
__device__ float g_g[SLOTS*NI];
__device__ float g_u[SLOTS*NI];
__device__ float g_y[SLOTS*Dm];
__device__ float g_scores[Ttok*NE];
__device__ int   g_counts[NE];
__device__ int   g_offsets[NE+1];
__device__ int   g_cursor[NE];
__device__ int   g_top_idx[Ttok*2];
__device__ float g_top_w[Ttok*2];
__device__ int   g_slot_token[SLOTS];
__device__ float g_slot_w[SLOTS];
__device__ int   g_slot_of[Ttok*2];
// tf32-rounded weights
__device__ float r_wq[Dm*Dm];
__device__ float r_wk[Dm*KVD];
__device__ float r_wv[Dm*KVD];
__device__ float r_wo[Dm*Dm];
__device__ float r_w1[NE*Dm*NI];
__device__ float r_w3[NE*Dm*NI];
__device__ float r_w2[NE*NI*Dm];

__device__ __forceinline__ unsigned f2tf(float x) {
    unsigned r; asm("cvt.rna.tf32.f32 %0, %1;" : "=r"(r) : "f"(x)); return r;
}
__device__ __forceinline__ float f2tff(float x) { return __uint_as_float(f2tf(x)); }
__device__ __forceinline__ void cp16(unsigned d, const void* s) {
    asm volatile("cp.async.cg.shared.global [%0], [%1], 16;" :: "r"(d), "l"(s));
}
__device__ __forceinline__ void cp_commit() {
    asm volatile("cp.async.commit_group;");
}
template<int N> __device__ __forceinline__ void cp_wait() {
    asm volatile("cp.async.wait_group %0;" :: "n"(N));
}

// ---------------- small kernels ----------------
__global__ void zero_kernel() {
    int i = threadIdx.x;
    if (i < NE) { g_counts[i] = 0; g_cursor[i] = 0; }
}

__global__ void roundcopy(const float* __restrict__ s, float* __restrict__ d, int n4) {
    int i = blockIdx.x*256 + threadIdx.x;
    if (i >= n4) return;
    float4 v = ((const float4*)s)[i];
    uint4 u;
    u.x = f2tf(v.x); u.y = f2tf(v.y); u.z = f2tf(v.z); u.w = f2tf(v.w);
    ((uint4*)d)[i] = u;
}

__global__ void rmsnorm_kernel(const float* __restrict__ in,
                               const float* __restrict__ w,
                               float* __restrict__ out) {
    int t = blockIdx.x;
    const float* row = in + (size_t)t*Dm;
    float ss = 0.f;
    for (int i = threadIdx.x; i < Dm; i += 256) { float v = row[i]; ss += v*v; }
    __shared__ float red[8];
    for (int o = 16; o; o >>= 1) ss += __shfl_xor_sync(0xffffffffu, ss, o);
    if ((threadIdx.x & 31) == 0) red[threadIdx.x >> 5] = ss;
    __syncthreads();
    float tot = 0.f;
    #pragma unroll
    for (int i = 0; i < 8; i++) tot += red[i];
    float inv = rsqrtf(tot * (1.f/(float)Dm) + 1e-5f);
    for (int i = threadIdx.x; i < Dm; i += 256)
        out[(size_t)t*Dm + i] = f2tff(row[i] * inv * w[i]);
}

// ---------------- tf32 GEMM, cp.async double-buffered ----------------
#define GA_STRIDE 36
#define GB_STRIDE 136
#define GA_BUF (128*GA_STRIDE)
#define GB_BUF (32*GB_STRIDE)
#define GEMM_SMEM ((2*GA_BUF + 2*GB_BUF)*4)

__global__ void __launch_bounds__(256, 2) tf32_gemm(
    const float* __restrict__ A, const float* __restrict__ B,
    float* __restrict__ C, int M, int N, int K,
    const float* __restrict__ addsrc, int mode,
    const float* __restrict__ B2, float* __restrict__ C2)
{
    extern __shared__ float dsm[];
    float* As = dsm;
    float* Bs = dsm + 2*GA_BUF;
    int cnt, off;
    if (mode == 0) {
        cnt = M; off = 0;
        if (blockIdx.z == 1) { B = B2; C = C2; }
    } else {
        int e = blockIdx.z;
        cnt = g_counts[e]; off = g_offsets[e];
        B += (size_t)e * K * N;
    }
    int bm = blockIdx.y * 128;
    if (bm >= cnt) return;
    int bn = blockIdx.x * 128;
    int tid = threadIdx.x;
    int lane = tid & 31, wid = tid >> 5;
    int warp_m = wid >> 2, warp_n = wid & 3;
    int lq = lane >> 2, lr = lane & 3;

    const float* aptr[4];
    #pragma unroll
    for (int r = 0; r < 4; r++) {
        int row = bm + r*32 + (tid >> 3);
        int re = row < cnt ? row : cnt - 1;
        if (mode == 1)      aptr[r] = g_h + (size_t)g_slot_token[off + re] * K;
        else if (mode == 2) aptr[r] = A + (size_t)(off + re) * K;
        else                aptr[r] = A + (size_t)re * K;
    }
    int ak4 = (tid & 7) * 4;
    int bk  = tid >> 5;
    int bn4 = lane * 4;
    const float* bsrc = B + (size_t)bk*N + bn + bn4;

    unsigned as_sm = (unsigned)__cvta_generic_to_shared(As);
    unsigned bs_sm = (unsigned)__cvta_generic_to_shared(Bs);
    unsigned a_dst0 = as_sm + (((tid>>3)*GA_STRIDE) + ak4)*4u;
    unsigned b_dst0 = bs_sm + ((bk*GB_STRIDE) + bn4)*4u;

    float acc[4][4][4];
    #pragma unroll
    for (int i=0;i<4;i++)
        #pragma unroll
        for(int j=0;j<4;j++)
            #pragma unroll
            for(int c=0;c<4;c++) acc[i][j][c]=0.f;

    int nkt = K >> 5;
    #pragma unroll
    for (int r = 0; r < 4; r++)
        cp16(a_dst0 + (unsigned)(r*32*GA_STRIDE)*4u, aptr[r] + ak4);
    #pragma unroll
    for (int r = 0; r < 4; r++)
        cp16(b_dst0 + (unsigned)(r*8*GB_STRIDE)*4u, bsrc + (size_t)(r*8)*N);
    cp_commit();

    for (int it = 0; it < nkt; it++) {
        int cur = it & 1;
        if (it + 1 < nkt) {
            int nb = (it + 1) & 1;
            int k0 = (it + 1) << 5;
            unsigned ad = a_dst0 + (unsigned)(nb*GA_BUF)*4u;
            unsigned bd = b_dst0 + (unsigned)(nb*GB_BUF)*4u;
            #pragma unroll
            for (int r = 0; r < 4; r++)
                cp16(ad + (unsigned)(r*32*GA_STRIDE)*4u, aptr[r] + k0 + ak4);
            #pragma unroll
            for (int r = 0; r < 4; r++)
                cp16(bd + (unsigned)(r*8*GB_STRIDE)*4u, bsrc + (size_t)(k0 + r*8)*N);
            cp_commit();
            cp_wait<1>();
        } else {
            cp_wait<0>();
        }
        __syncthreads();
        const float* Ac = As + cur*GA_BUF;
        const float* Bc = Bs + cur*GB_BUF;
        #pragma unroll
        for (int ks = 0; ks < 4; ks++) {
            int k8 = ks*8;
            unsigned af[4][4], bf[4][2];
            #pragma unroll
            for (int mt=0; mt<4; mt++) {
                int m0 = warp_m*64 + mt*16;
                const float* p = &Ac[(m0+lq)*GA_STRIDE + k8 + lr];
                af[mt][0] = __float_as_uint(p[0]);
                af[mt][1] = __float_as_uint(p[8*GA_STRIDE]);
                af[mt][2] = __float_as_uint(p[4]);
                af[mt][3] = __float_as_uint(p[8*GA_STRIDE+4]);
            }
            #pragma unroll
            for (int nt=0; nt<4; nt++) {
                int n0 = warp_n*32 + nt*8 + lq;
                bf[nt][0] = __float_as_uint(Bc[(k8+lr)*GB_STRIDE + n0]);
                bf[nt][1] = __float_as_uint(Bc[(k8+4+lr)*GB_STRIDE + n0]);
            }
            #pragma unroll
            for (int mt=0; mt<4; mt++)
                #pragma unroll
                for (int nt=0; nt<4; nt++) {
                    asm volatile(
                        "mma.sync.aligned.m16n8k8.row.col.f32.tf32.tf32.f32 "
                        "{%0,%1,%2,%3}, {%4,%5,%6,%7}, {%8,%9}, {%0,%1,%2,%3};"
                        : "+f"(acc[mt][nt][0]), "+f"(acc[mt][nt][1]),
                          "+f"(acc[mt][nt][2]), "+f"(acc[mt][nt][3])
                        : "r"(af[mt][0]), "r"(af[mt][1]), "r"(af[mt][2]), "r"(af[mt][3]),
                          "r"(bf[nt][0]), "r"(bf[nt][1]));
                }
        }
        __syncthreads();
    }
    #pragma unroll
    for (int mt=0; mt<4; mt++) {
        int row0 = bm + warp_m*64 + mt*16 + lq;
        #pragma unroll
        for (int half=0; half<2; half++) {
            int row = row0 + half*8;
            if (row >= cnt) continue;
            size_t crow = (size_t)(off + row);
            #pragma unroll
            for (int nt=0; nt<4; nt++) {
                int col = bn + warp_n*32 + nt*8 + 2*lr;
                float2 v;
                v.x = acc[mt][nt][half*2+0];
                v.y = acc[mt][nt][half*2+1];
                if (addsrc) {
                    float2 s = *(const float2*)(addsrc + crow*N + col);
                    v.x += s.x; v.y += s.y;
                }
                *(float2*)(C + crow*N + col) = v;
            }
        }
    }
}

// ---------------- RoPE (rounds q,k; also rounds v) ----------------
__global__ void rope_kernel() {
    int idx = blockIdx.x*256 + threadIdx.x;
    const int totq = Ttok*NH*(HDv/2);
    const int totk = totq + Ttok*KVHv*(HDv/2);
    const int tot  = totk + Ttok*(KVD/2);
    if (idx >= tot) return;
    if (idx >= totk) {
        int id2 = idx - totk;
        float* p = g_v + (size_t)id2*2;
        p[0] = f2tff(p[0]); p[1] = f2tff(p[1]);
        return;
    }
    float* base; int t, i;
    if (idx < totq) {
        i = idx & 63;
        int hh = (idx >> 6) & (NH-1);
        t = idx >> 10;
        base = g_q + (size_t)t*Dm + hh*HDv + 2*i;
    } else {
        int id2 = idx - totq;
        i = id2 & 63;
        int hh = (id2 >> 6) & (KVHv-1);
        t = id2 >> 8;
        base = g_k + (size_t)t*KVD + hh*HDv + 2*i;
    }
    int pos = t & (Lq-1);
    float inv = exp2f(-(float)i * (13.287712379549449f/64.f));
    float ang = (float)pos * inv;
    float c = cosf(ang), s = sinf(ang);
    float xr = base[0], xi = base[1];
    base[0] = f2tff(xr*c - xi*s);
    base[1] = f2tff(xr*s + xi*c);
}

// ---------------- tensor-core flash attention, cp.async K/V ----------------
#define QPAD 132
#define VPAD 136
#define PPAD 36
#define AT_QS 0
#define AT_KS (64*QPAD)                       /* 8448  */
#define AT_KBUF (32*QPAD)                     /* 4224  */
#define AT_VS (AT_KS + 2*AT_KBUF)             /* 16896 */
#define AT_VBUF (32*VPAD)                     /* 4352  */
#define AT_PS (AT_VS + 2*AT_VBUF)             /* 25600 */
#define AT_SMEM_WORDS (AT_PS + 64*PPAD)       /* 27904 */

__global__ void __launch_bounds__(128) attn_mma_kernel() {
    extern __shared__ float sm[];
    int b = blockIdx.z, h = blockIdx.y;
    int q0 = blockIdx.x * 64;
    int kvh = h >> 2;
    int tid = threadIdx.x;
    int lane = tid & 31, w = tid >> 5;
    int lq = lane >> 2, lr = lane & 3;
    const float scale = 0.08838834764831845f;

    unsigned sm_base = (unsigned)__cvta_generic_to_shared(sm);

    // prologue: cp.async K/V tile 0 -> buf 0 (full 32 rows x 128 cols)
    for (int idx = tid; idx < 32*32; idx += 128) {
        int row = idx >> 5, c4 = (idx & 31) * 4;
        size_t goff = (size_t)(b*Lq + row)*KVD + kvh*HDv + c4;
        cp16(sm_base + (unsigned)(AT_KS + row*QPAD + c4)*4u, g_k + goff);
        cp16(sm_base + (unsigned)(AT_VS + row*VPAD + c4)*4u, g_v + goff);
    }
    cp_commit();

    // load Q tile raw (64 rows x 128 cols, already tf32-rounded)
    for (int idx = tid; idx < 64*32; idx += 128) {
        int row = idx >> 5, c4 = (idx & 31) * 4;
        float4 qv = *(const float4*)(g_q + (size_t)(b*Lq + q0 + row)*Dm + h*HDv + c4);
        *(float4*)&sm[AT_QS + row*QPAD + c4] = qv;
    }

    float o[16][4];
    #pragma unroll
    for (int nt=0;nt<16;nt++){o[nt][0]=0.f;o[nt][1]=0.f;o[nt][2]=0.f;o[nt][3]=0.f;}
    float m0 = -1e30f, m1 = -1e30f, l0 = 0.f, l1 = 0.f;
    int row_base = q0 + w*16;
    int ntiles = (q0 + 64) / 32;

    for (int kt = 0; kt < ntiles; kt++) {
        int cur = kt & 1;
        if (kt + 1 < ntiles) {
            int nb = (kt + 1) & 1;
            int nbase = (kt + 1) * 32;
            for (int idx = tid; idx < 32*32; idx += 128) {
                int row = idx >> 5, c4 = (idx & 31) * 4;
                size_t goff = (size_t)(b*Lq + nbase + row)*KVD + kvh*HDv + c4;
                cp16(sm_base + (unsigned)(AT_KS + nb*AT_KBUF + row*QPAD + c4)*4u, g_k + goff);
                cp16(sm_base + (unsigned)(AT_VS + nb*AT_VBUF + row*VPAD + c4)*4u, g_v + goff);
            }
            cp_commit();
            cp_wait<1>();
        } else {
            cp_wait<0>();
        }
        __syncthreads();
        int base = kt * 32;
        const float* Kc = sm + AT_KS + cur*AT_KBUF;
        const float* Vc = sm + AT_VS + cur*AT_VBUF;

        // S = Q K^T
        float s[4][4];
        #pragma unroll
        for (int nt=0;nt<4;nt++){s[nt][0]=0.f;s[nt][1]=0.f;s[nt][2]=0.f;s[nt][3]=0.f;}
        #pragma unroll
        for (int ks = 0; ks < 16; ks++) {
            int k8 = ks*8;
            const float* qp = &sm[AT_QS + (w*16+lq)*QPAD + k8 + lr];
            unsigned a0 = __float_as_uint(qp[0]);
            unsigned a1 = __float_as_uint(qp[8*QPAD]);
            unsigned a2 = __float_as_uint(qp[4]);
            unsigned a3 = __float_as_uint(qp[8*QPAD+4]);
            #pragma unroll
            for (int nt=0; nt<4; nt++) {
                unsigned b0 = __float_as_uint(Kc[(nt*8+lq)*QPAD + k8 + lr]);
                unsigned b1 = __float_as_uint(Kc[(nt*8+lq)*QPAD + k8 + lr + 4]);
                asm volatile(
                    "mma.sync.aligned.m16n8k8.row.col.f32.tf32.tf32.f32 "
                    "{%0,%1,%2,%3}, {%4,%5,%6,%7}, {%8,%9}, {%0,%1,%2,%3};"
                    : "+f"(s[nt][0]), "+f"(s[nt][1]), "+f"(s[nt][2]), "+f"(s[nt][3])
                    : "r"(a0), "r"(a1), "r"(a2), "r"(a3), "r"(b0), "r"(b1));
            }
        }
        #pragma unroll
        for (int nt=0; nt<4; nt++) {
            s[nt][0]*=scale; s[nt][1]*=scale; s[nt][2]*=scale; s[nt][3]*=scale;
        }

        if (base + 31 > row_base) {
            int i0 = row_base + lq, i1 = row_base + lq + 8;
            #pragma unroll
            for (int nt=0; nt<4; nt++) {
                int j = base + nt*8 + 2*lr;
                if (j   > i0) s[nt][0] = -1e30f;
                if (j+1 > i0) s[nt][1] = -1e30f;
                if (j   > i1) s[nt][2] = -1e30f;
                if (j+1 > i1) s[nt][3] = -1e30f;
            }
        }

        float mx0 = -1e30f, mx1 = -1e30f;
        #pragma unroll
        for (int nt=0; nt<4; nt++) {
            mx0 = fmaxf(mx0, fmaxf(s[nt][0], s[nt][1]));
            mx1 = fmaxf(mx1, fmaxf(s[nt][2], s[nt][3]));
        }
        mx0 = fmaxf(mx0, __shfl_xor_sync(0xffffffffu, mx0, 1));
        mx0 = fmaxf(mx0, __shfl_xor_sync(0xffffffffu, mx0, 2));
        mx1 = fmaxf(mx1, __shfl_xor_sync(0xffffffffu, mx1, 1));
        mx1 = fmaxf(mx1, __shfl_xor_sync(0xffffffffu, mx1, 2));
        float mn0 = fmaxf(m0, mx0), mn1 = fmaxf(m1, mx1);
        float al0 = __expf(m0 - mn0), al1 = __expf(m1 - mn1);
        float rs0 = 0.f, rs1 = 0.f;
        #pragma unroll
        for (int nt=0; nt<4; nt++) {
            s[nt][0] = __expf(s[nt][0] - mn0);
            s[nt][1] = __expf(s[nt][1] - mn0);
            s[nt][2] = __expf(s[nt][2] - mn1);
            s[nt][3] = __expf(s[nt][3] - mn1);
            rs0 += s[nt][0] + s[nt][1];
            rs1 += s[nt][2] + s[nt][3];
        }
        rs0 += __shfl_xor_sync(0xffffffffu, rs0, 1);
        rs0 += __shfl_xor_sync(0xffffffffu, rs0, 2);
        rs1 += __shfl_xor_sync(0xffffffffu, rs1, 1);
        rs1 += __shfl_xor_sync(0xffffffffu, rs1, 2);
        l0 = l0*al0 + rs0;
        l1 = l1*al1 + rs1;
        m0 = mn0; m1 = mn1;
        #pragma unroll
        for (int nt=0; nt<16; nt++) {
            o[nt][0]*=al0; o[nt][1]*=al0; o[nt][2]*=al1; o[nt][3]*=al1;
        }

        #pragma unroll
        for (int nt=0; nt<4; nt++) {
            float* p0 = &sm[AT_PS + (w*16+lq)*PPAD + nt*8 + 2*lr];
            p0[0] = __uint_as_float(f2tf(s[nt][0]));
            p0[1] = __uint_as_float(f2tf(s[nt][1]));
            float* p1 = &sm[AT_PS + (w*16+lq+8)*PPAD + nt*8 + 2*lr];
            p1[0] = __uint_as_float(f2tf(s[nt][2]));
            p1[1] = __uint_as_float(f2tf(s[nt][3]));
        }
        __syncwarp();

        #pragma unroll
        for (int ks = 0; ks < 4; ks++) {
            int k8 = ks*8;
            const float* pp = &sm[AT_PS + (w*16+lq)*PPAD + k8 + lr];
            unsigned a0 = __float_as_uint(pp[0]);
            unsigned a1 = __float_as_uint(pp[8*PPAD]);
            unsigned a2 = __float_as_uint(pp[4]);
            unsigned a3 = __float_as_uint(pp[8*PPAD+4]);
            #pragma unroll
            for (int nt=0; nt<16; nt++) {
                unsigned b0 = __float_as_uint(Vc[(k8+lr)*VPAD + nt*8 + lq]);
                unsigned b1 = __float_as_uint(Vc[(k8+lr+4)*VPAD + nt*8 + lq]);
                asm volatile(
                    "mma.sync.aligned.m16n8k8.row.col.f32.tf32.tf32.f32 "
                    "{%0,%1,%2,%3}, {%4,%5,%6,%7}, {%8,%9}, {%0,%1,%2,%3};"
                    : "+f"(o[nt][0]), "+f"(o[nt][1]), "+f"(o[nt][2]), "+f"(o[nt][3])
                    : "r"(a0), "r"(a1), "r"(a2), "r"(a3), "r"(b0), "r"(b1));
            }
        }
        __syncthreads();
    }

    float inv0 = 1.f / l0, inv1 = 1.f / l1;
    int t0 = b*Lq + row_base + lq;
    #pragma unroll
    for (int nt=0; nt<16; nt++) {
        int col = h*HDv + nt*8 + 2*lr;
        float2 v0 = make_float2(f2tff(o[nt][0]*inv0), f2tff(o[nt][1]*inv0));
        float2 v1 = make_float2(f2tff(o[nt][2]*inv1), f2tff(o[nt][3]*inv1));
        *(float2*)(g_ao + (size_t)t0*Dm + col) = v0;
        *(float2*)(g_ao + (size_t)(t0+8)*Dm + col) = v1;
    }
}

// ---------------- gating ----------------
__global__ void gate_kernel(const float* __restrict__ gw) {
    int t = blockIdx.x;
    int warp = threadIdx.x >> 5, lane = threadIdx.x & 31;
    const float* row = g_h + (size_t)t*Dm;
    float s = 0.f;
    for (int i = lane; i < Dm; i += 32) s += row[i] * gw[(size_t)i*NE + warp];
    for (int o = 16; o; o >>= 1) s += __shfl_xor_sync(0xffffffffu, s, o);
    __shared__ float logits[NE];
    if (lane == 0) logits[warp] = s;
    __syncthreads();
    if (threadIdx.x == 0) {
        float mx = logits[0];
        for (int e = 1; e < NE; e++) mx = fmaxf(mx, logits[e]);
        float ex[NE]; float sum = 0.f;
        for (int e = 0; e < NE; e++) { ex[e] = expf(logits[e]-mx); sum += ex[e]; }
        float invs = 1.f/sum;
        float sc[NE];
        for (int e = 0; e < NE; e++) { sc[e] = ex[e]*invs; g_scores[t*NE+e] = sc[e]; }
        int e0 = 0; float m0 = sc[0];
        for (int e = 1; e < NE; e++) if (sc[e] > m0) { m0 = sc[e]; e0 = e; }
        int e1 = -1; float m1 = -1.f;
        for (int e = 0; e < NE; e++) if (e != e0 && sc[e] > m1) { m1 = sc[e]; e1 = e; }
        float wsum = m0 + m1;
        g_top_idx[t*2]   = e0;  g_top_idx[t*2+1] = e1;
        g_top_w[t*2]     = m0/wsum;
        g_top_w[t*2+1]   = m1/wsum;
        atomicAdd(&g_counts[e0], 1);
        atomicAdd(&g_counts[e1], 1);
    }
}

__global__ void finalize_gate_kernel(float* aux_out) {
    int warp = threadIdx.x >> 5, lane = threadIdx.x & 31;
    float s = 0.f;
    for (int t = lane; t < Ttok; t += 32) s += g_scores[t*NE + warp];
    for (int o = 16; o; o >>= 1) s += __shfl_xor_sync(0xffffffffu, s, o);
    __shared__ float ps[NE];
    if (lane == 0) ps[warp] = s;
    __syncthreads();
    if (threadIdx.x == 0) {
        int off = 0; float aux = 0.f;
        for (int e = 0; e < NE; e++) {
            g_offsets[e] = off; off += g_counts[e];
            float f = (float)g_counts[e] / (float)Ttok;
            float p = ps[e] / (float)Ttok;
            aux += f * p;
        }
        g_offsets[NE] = off;
        aux_out[0] = 0.01f * (float)NE * aux;
    }
}

__global__ void scatter_kernel() {
    int t = blockIdx.x*256 + threadIdx.x;
    if (t >= Ttok) return;
    for (int j = 0; j < 2; j++) {
        int e = g_top_idx[t*2+j];
        int pos = atomicAdd(&g_cursor[e], 1);
        int slot = g_offsets[e] + pos;
        g_slot_token[slot] = t;
        g_slot_w[slot] = g_top_w[t*2+j];
        g_slot_of[t*2+j] = slot;
    }
}

// ---------------- silu(g)*u (rounded for w2 GEMM) ----------------
__global__ void silu_mul_kernel() {
    size_t i = ((size_t)blockIdx.x*256 + threadIdx.x)*4;
    float4 g = *(float4*)(g_g + i);
    float4 u = *(float4*)(g_u + i);
    g.x = f2tff(g.x / (1.f + __expf(-g.x)) * u.x);
    g.y = f2tff(g.y / (1.f + __expf(-g.y)) * u.y);
    g.z = f2tff(g.z / (1.f + __expf(-g.z)) * u.z);
    g.w = f2tff(g.w / (1.f + __expf(-g.w)) * u.w);
    *(float4*)(g_g + i) = g;
}

__global__ void final_add_kernel(float* __restrict__ out) {
    int t = blockIdx.x;
    int s0 = g_slot_of[t*2], s1 = g_slot_of[t*2+1];
    float w0 = g_slot_w[s0], w1 = g_slot_w[s1];
    for (int i = threadIdx.x*4; i < Dm; i += 256*4) {
        float4 a  = *(float4*)(out + (size_t)t*Dm + i);
        float4 y0 = *(const float4*)(g_y + (size_t)s0*Dm + i);
        float4 y1 = *(const float4*)(g_y + (size_t)s1*Dm + i);
        a.x += w0*y0.x + w1*y1.x;
        a.y += w0*y0.y + w1*y1.y;
        a.z += w0*y0.z + w1*y1.z;
        a.w += w0*y0.w + w1*y1.w;
        *(float4*)(out + (size_t)t*Dm + i) = a;
    }
}

// ---------------- launch ----------------
extern "C" void kernel_launch(void* const* d_in, const int* in_sizes, int n_in,
                              void* d_out, int out_size) {
    const float* x           = (const float*)d_in[0];
    const float* w_q         = (const float*)d_in[1];
    const float* w_k         = (const float*)d_in[2];
    const float* w_v         = (const float*)d_in[3];
    const float* w_o         = (const float*)d_in[4];
    const float* attn_norm_w = (const float*)d_in[5];
    const float* moe_norm_w  = (const float*)d_in[6];
    const float* gate_w      = (const float*)d_in[7];
    const float* w1          = (const float*)d_in[8];
    const float* w3          = (const float*)d_in[9];
    const float* w2          = (const float*)d_in[10];
    float* out = (float*)d_out;

    float *ph, *pq, *pk, *pv, *pao, *pg, *pu, *py;
    float *pwq, *pwk, *pwv, *pwo, *pw1, *pw3, *pw2;
    cudaGetSymbolAddress((void**)&ph,  g_h);
    cudaGetSymbolAddress((void**)&pq,  g_q);
    cudaGetSymbolAddress((void**)&pk,  g_k);
    cudaGetSymbolAddress((void**)&pv,  g_v);
    cudaGetSymbolAddress((void**)&pao, g_ao);
    cudaGetSymbolAddress((void**)&pg,  g_g);
    cudaGetSymbolAddress((void**)&pu,  g_u);
    cudaGetSymbolAddress((void**)&py,  g_y);
    cudaGetSymbolAddress((void**)&pwq, r_wq);
    cudaGetSymbolAddress((void**)&pwk, r_wk);
    cudaGetSymbolAddress((void**)&pwv, r_wv);
    cudaGetSymbolAddress((void**)&pwo, r_wo);
    cudaGetSymbolAddress((void**)&pw1, r_w1);
    cudaGetSymbolAddress((void**)&pw3, r_w3);
    cudaGetSymbolAddress((void**)&pw2, r_w2);

    static int attr_set = 0;
    const int attn_smem = AT_SMEM_WORDS * 4;
    if (!attr_set) {
        cudaFuncSetAttribute(attn_mma_kernel,
                             cudaFuncAttributeMaxDynamicSharedMemorySize, attn_smem);
        cudaFuncSetAttribute(tf32_gemm,
                             cudaFuncAttributeMaxDynamicSharedMemorySize, GEMM_SMEM);
        attr_set = 1;
    }

    roundcopy<<<(Dm*Dm/4 + 255)/256, 256>>>(w_q, pwq, Dm*Dm/4);
    roundcopy<<<(Dm*KVD/4 + 255)/256, 256>>>(w_k, pwk, Dm*KVD/4);
    roundcopy<<<(Dm*KVD/4 + 255)/256, 256>>>(w_v, pwv, Dm*KVD/4);
    roundcopy<<<(Dm*Dm/4 + 255)/256, 256>>>(w_o, pwo, Dm*Dm/4);
    roundcopy<<<(NE*Dm*NI/4 + 255)/256, 256>>>(w1, pw1, NE*Dm*NI/4);
    roundcopy<<<(NE*Dm*NI/4 + 255)/256, 256>>>(w3, pw3, NE*Dm*NI/4);
    roundcopy<<<(NE*NI*Dm/4 + 255)/256, 256>>>(w2, pw2, NE*NI*Dm/4);

    zero_kernel<<<1, 32>>>();
    rmsnorm_kernel<<<Ttok, 256>>>(x, attn_norm_w, ph);
    tf32_gemm<<<dim3(Dm/128, Ttok/128, 1), 256, GEMM_SMEM>>>(ph, pwq, pq, Ttok, Dm, Dm,
                                                  nullptr, 0, nullptr, nullptr);
    tf32_gemm<<<dim3(KVD/128, Ttok/128, 2), 256, GEMM_SMEM>>>(ph, pwk, pk, Ttok, KVD, Dm,
                                                   nullptr, 0, pwv, pv);
    {
        int tot = Ttok*NH*(HDv/2) + Ttok*KVHv*(HDv/2) + Ttok*(KVD/2);
        rope_kernel<<<(tot + 255)/256, 256>>>();
    }
    attn_mma_kernel<<<dim3(Lq/64, NH, Bq), 128, attn_smem>>>();
    tf32_gemm<<<dim3(Dm/128, Ttok/128, 1), 256, GEMM_SMEM>>>(pao, pwo, out, Ttok, Dm, Dm,
                                                  x, 0, nullptr, nullptr);
    rmsnorm_kernel<<<Ttok, 256>>>(out, moe_norm_w, ph);
    gate_kernel<<<Ttok, 256>>>(gate_w);
    finalize_gate_kernel<<<1, 256>>>(out + (size_t)Ttok*Dm);
    scatter_kernel<<<(Ttok + 255)/256, 256>>>();
    tf32_gemm<<<dim3(NI/128, SLOTS/128, NE), 256, GEMM_SMEM>>>(nullptr, pw1, pg, 0, NI, Dm,
                                                    nullptr, 1, nullptr, nullptr);
    tf32_gemm<<<dim3(NI/128, SLOTS/128, NE), 256, GEMM_SMEM>>>(nullptr, pw3, pu, 0, NI, Dm,
                                                    nullptr, 1, nullptr, nullptr);
    silu_mul_kernel<<<SLOTS*NI/1024, 256>>>();
    tf32_gemm<<<dim3(Dm/128, SLOTS/128, NE), 256, GEMM_SMEM>>>(pg, pw2, py, 0, Dm, NI,
                                                    nullptr, 2, nullptr, nullptr);
    final_add_kernel<<<Ttok, 256>>>(out);
}